// round 1
// baseline (speedup 1.0000x reference)
#include <cuda_runtime.h>
#include <math.h>

#define Bsz 512
#define Ssz 256
#define Esz 256
#define Hsz 512
#define Gsz 1536   // 3*H
#define Lsz 8

// Scratch: precomputed input-side gate projections gi[s][b][g] (805 MB), and
// ping-pong hidden state h[2][B][H]. Device globals: allowed (no runtime alloc).
__device__ float g_gi[(size_t)Ssz * Bsz * Gsz];
__device__ float g_h[2][Bsz * Hsz];

// ---------------- packed f32x2 helpers (Blackwell FFMA2 path) ----------------
__device__ __forceinline__ unsigned long long pack2(float x, float y) {
    unsigned long long r;
    asm("mov.b64 %0, {%1, %2};" : "=l"(r) : "f"(x), "f"(y));
    return r;
}
__device__ __forceinline__ void fma2(unsigned long long& d, unsigned long long a,
                                     unsigned long long b) {
    asm("fma.rn.f32x2 %0, %1, %2, %0;" : "+l"(d) : "l"(a), "l"(b));
}
__device__ __forceinline__ float2 unpack2(unsigned long long v) {
    float2 r;
    asm("mov.b64 {%0, %1}, %2;" : "=f"(r.x), "=f"(r.y) : "l"(v));
    return r;
}

__device__ __forceinline__ float sigmoidf_(float x) {
    return 1.0f / (1.0f + expf(-x));
}

// ============================================================================
// Kernel 1: gi = x @ W_ih^T + b_ih   -> g_gi[(s*B+b)*G + g]
// M = S*B = 131072 (row m -> s = m>>9, b = m&511), N = 1536, K = 256.
// 128x128 tile, BK=16, 256 threads, 8x8 per-thread tile (rows in f32x2 pairs).
// ============================================================================
__global__ void __launch_bounds__(256) gi_gemm_kernel(
    const float* __restrict__ x, const float* __restrict__ W_ih,
    const float* __restrict__ b_ih) {
    __shared__ float As[16][132];   // [k][row], padded
    __shared__ float Bs[16][132];

    const int m0 = blockIdx.x * 128;
    const int n0 = blockIdx.y * 128;
    const int tid = threadIdx.x;
    const int tx = tid % 16;   // 8 output cols each
    const int ty = tid / 16;   // 8 output rows each

    unsigned long long acc[4][8];   // [row-pair][col]
#pragma unroll
    for (int i = 0; i < 4; i++)
#pragma unroll
        for (int j = 0; j < 8; j++) acc[i][j] = 0ULL;

    for (int k0 = 0; k0 < Esz; k0 += 16) {
#pragma unroll
        for (int t = 0; t < 2; t++) {
            int idx = t * 256 + tid;   // 0..511 -> 128 rows * 4 float4
            int row = idx >> 2;
            int kq  = idx & 3;
            int m = m0 + row;
            int s = m >> 9;
            int b = m & (Bsz - 1);
            float4 v = *(const float4*)(x + ((size_t)b * Ssz + s) * Esz + k0 + kq * 4);
            As[kq * 4 + 0][row] = v.x; As[kq * 4 + 1][row] = v.y;
            As[kq * 4 + 2][row] = v.z; As[kq * 4 + 3][row] = v.w;
            float4 w = *(const float4*)(W_ih + (size_t)(n0 + row) * Esz + k0 + kq * 4);
            Bs[kq * 4 + 0][row] = w.x; Bs[kq * 4 + 1][row] = w.y;
            Bs[kq * 4 + 2][row] = w.z; Bs[kq * 4 + 3][row] = w.w;
        }
        __syncthreads();
#pragma unroll
        for (int kk = 0; kk < 16; kk++) {
            unsigned long long a2[4];
#pragma unroll
            for (int i = 0; i < 4; i++) {
                float2 av = *(const float2*)&As[kk][ty * 8 + i * 2];
                a2[i] = pack2(av.x, av.y);
            }
            float4 bva = *(const float4*)&Bs[kk][tx * 8];
            float4 bvb = *(const float4*)&Bs[kk][tx * 8 + 4];
            float bv[8] = {bva.x, bva.y, bva.z, bva.w, bvb.x, bvb.y, bvb.z, bvb.w};
#pragma unroll
            for (int j = 0; j < 8; j++) {
                unsigned long long bd = pack2(bv[j], bv[j]);
#pragma unroll
                for (int i = 0; i < 4; i++) fma2(acc[i][j], a2[i], bd);
            }
        }
        __syncthreads();
    }

    float bias[8];
#pragma unroll
    for (int j = 0; j < 8; j++) bias[j] = b_ih[n0 + tx * 8 + j];

#pragma unroll
    for (int i = 0; i < 4; i++) {
        float lo[8], hi[8];
#pragma unroll
        for (int j = 0; j < 8; j++) {
            float2 v = unpack2(acc[i][j]);
            lo[j] = v.x + bias[j];
            hi[j] = v.y + bias[j];
        }
        int m_lo = m0 + ty * 8 + i * 2;
        float* p0 = g_gi + (size_t)m_lo * Gsz + n0 + tx * 8;
        float* p1 = p0 + Gsz;
        *(float4*)(p0)     = make_float4(lo[0], lo[1], lo[2], lo[3]);
        *(float4*)(p0 + 4) = make_float4(lo[4], lo[5], lo[6], lo[7]);
        *(float4*)(p1)     = make_float4(hi[0], hi[1], hi[2], hi[3]);
        *(float4*)(p1 + 4) = make_float4(hi[4], hi[5], hi[6], hi[7]);
    }
}

// ============================================================================
// Kernel 2: one GRU time step, fused GEMM + gate nonlinearity.
// Block tile: 32 batch x 64 hidden x 3 gates. Grid (16, 8) = 128 blocks.
// 128 threads, per-thread 4 batch x 4 hidden x 3 gates (f32x2 pairs on hidden).
// ============================================================================
__global__ void __launch_bounds__(128) gru_step_kernel(
    const float* __restrict__ W_hh, const float* __restrict__ b_hh,
    int s, int ping) {
    __shared__ float Hs[16][36];        // [k][batch-row], padded
    __shared__ float Ws[3][16][68];     // [gate][k][j], padded

    const float* __restrict__ h_in  = g_h[ping];
    float* __restrict__ h_out = g_h[ping ^ 1];
    const float* __restrict__ gi_s = g_gi + (size_t)s * Bsz * Gsz;

    const int b0 = blockIdx.x * 32;
    const int j0 = blockIdx.y * 64;
    const int tid = threadIdx.x;
    const int tx = tid % 16;   // 4 hidden cols each
    const int ty = tid / 16;   // 4 batch rows each (ty in 0..7)

    unsigned long long acc[3][4][2];   // [gate][batch][j-pair]
#pragma unroll
    for (int g = 0; g < 3; g++)
#pragma unroll
        for (int i = 0; i < 4; i++) { acc[g][i][0] = 0ULL; acc[g][i][1] = 0ULL; }

    for (int k0 = 0; k0 < Hsz; k0 += 16) {
        {   // Hs: 32 rows x 16 k = 128 float4 -> 1 per thread
            int row = tid >> 2;
            int kq  = tid & 3;
            float4 v = *(const float4*)(h_in + (size_t)(b0 + row) * Hsz + k0 + kq * 4);
            Hs[kq * 4 + 0][row] = v.x; Hs[kq * 4 + 1][row] = v.y;
            Hs[kq * 4 + 2][row] = v.z; Hs[kq * 4 + 3][row] = v.w;
        }
#pragma unroll
        for (int t = 0; t < 6; t++) {   // Ws: 192 rows x 16 k = 768 float4
            int idx = t * 128 + tid;
            int row = idx >> 2;        // 0..191 = gate*64 + local j
            int kq  = idx & 3;
            int g  = row >> 6;
            int jr = row & 63;
            float4 v = *(const float4*)(W_hh + (size_t)(g * Hsz + j0 + jr) * Hsz + k0 + kq * 4);
            Ws[g][kq * 4 + 0][jr] = v.x; Ws[g][kq * 4 + 1][jr] = v.y;
            Ws[g][kq * 4 + 2][jr] = v.z; Ws[g][kq * 4 + 3][jr] = v.w;
        }
        __syncthreads();
#pragma unroll
        for (int kk = 0; kk < 16; kk++) {
            float4 hv = *(const float4*)&Hs[kk][ty * 4];
            unsigned long long hd[4];
            hd[0] = pack2(hv.x, hv.x); hd[1] = pack2(hv.y, hv.y);
            hd[2] = pack2(hv.z, hv.z); hd[3] = pack2(hv.w, hv.w);
#pragma unroll
            for (int g = 0; g < 3; g++) {
                float4 wv = *(const float4*)&Ws[g][kk][tx * 4];
                unsigned long long w0 = pack2(wv.x, wv.y);
                unsigned long long w1 = pack2(wv.z, wv.w);
#pragma unroll
                for (int i = 0; i < 4; i++) {
                    fma2(acc[g][i][0], hd[i], w0);
                    fma2(acc[g][i][1], hd[i], w1);
                }
            }
        }
        __syncthreads();
    }

    // Epilogue: GRU gate math, write h_out
#pragma unroll
    for (int i = 0; i < 4; i++) {
        int b = b0 + ty * 4 + i;
        const float* gib = gi_s + (size_t)b * Gsz;
#pragma unroll
        for (int jp = 0; jp < 2; jp++) {
            float2 gr = unpack2(acc[0][i][jp]);
            float2 gz = unpack2(acc[1][i][jp]);
            float2 gn = unpack2(acc[2][i][jp]);
#pragma unroll
            for (int q = 0; q < 2; q++) {
                int j = j0 + tx * 4 + jp * 2 + q;
                float vr = (q ? gr.y : gr.x) + b_hh[j];
                float vz = (q ? gz.y : gz.x) + b_hh[Hsz + j];
                float vn = (q ? gn.y : gn.x) + b_hh[2 * Hsz + j];
                float r = sigmoidf_(gib[j] + vr);
                float z = sigmoidf_(gib[Hsz + j] + vz);
                float n = tanhf(gib[2 * Hsz + j] + r * vn);
                float hp = h_in[(size_t)b * Hsz + j];
                h_out[(size_t)b * Hsz + j] = (1.0f - z) * n + z * hp;
            }
        }
    }
}

// ============================================================================
// Kernel 3: logits = h @ W_out^T + b_out, softmax over L=8. One warp per row.
// ============================================================================
__global__ void __launch_bounds__(256) out_kernel(
    const float* __restrict__ W_out, const float* __restrict__ b_out,
    float* __restrict__ out) {
    int gw   = (blockIdx.x * blockDim.x + threadIdx.x) >> 5;
    int lane = threadIdx.x & 31;
    if (gw >= Bsz) return;
    const float* h = g_h[0] + (size_t)gw * Hsz;

    float acc[Lsz];
#pragma unroll
    for (int l = 0; l < Lsz; l++) acc[l] = 0.0f;
    for (int j = lane; j < Hsz; j += 32) {
        float hv = h[j];
#pragma unroll
        for (int l = 0; l < Lsz; l++) acc[l] += hv * W_out[l * Hsz + j];
    }
#pragma unroll
    for (int l = 0; l < Lsz; l++)
#pragma unroll
        for (int o = 16; o > 0; o >>= 1)
            acc[l] += __shfl_xor_sync(0xffffffff, acc[l], o);

    if (lane == 0) {
        float logits[Lsz];
        float mx = -1e30f;
#pragma unroll
        for (int l = 0; l < Lsz; l++) {
            logits[l] = acc[l] + b_out[l];
            mx = fmaxf(mx, logits[l]);
        }
        float sum = 0.0f;
#pragma unroll
        for (int l = 0; l < Lsz; l++) {
            logits[l] = expf(logits[l] - mx);
            sum += logits[l];
        }
        float inv = 1.0f / sum;
#pragma unroll
        for (int l = 0; l < Lsz; l++) out[(size_t)gw * Lsz + l] = logits[l] * inv;
    }
}

__global__ void zero_h_kernel() {
    int i = blockIdx.x * blockDim.x + threadIdx.x;
    if (i < Bsz * Hsz) g_h[0][i] = 0.0f;
}

// ============================================================================
extern "C" void kernel_launch(void* const* d_in, const int* in_sizes, int n_in,
                              void* d_out, int out_size) {
    const float* x     = (const float*)d_in[0];
    const float* W_ih  = (const float*)d_in[1];
    const float* W_hh  = (const float*)d_in[2];
    const float* b_ih  = (const float*)d_in[3];
    const float* b_hh  = (const float*)d_in[4];
    const float* W_out = (const float*)d_in[5];
    const float* b_out = (const float*)d_in[6];
    float* out = (float*)d_out;

    zero_h_kernel<<<(Bsz * Hsz + 255) / 256, 256>>>();
    gi_gemm_kernel<<<dim3((Ssz * Bsz) / 128, Gsz / 128), 256>>>(x, W_ih, b_ih);
    for (int s = 0; s < Ssz; s++) {
        gru_step_kernel<<<dim3(Bsz / 32, Hsz / 64), 128>>>(W_hh, b_hh, s, s & 1);
    }
    out_kernel<<<(Bsz * 32 + 255) / 256, 256>>>(W_out, b_out, out);
}